// round 4
// baseline (speedup 1.0000x reference)
#include <cuda_runtime.h>

#define N_TOT   16384      // B*H*W
#define C_DIM   256
#define K_CODES 8192
#define HW      1024
#define B_DIM   16

// Device scratch (no allocations allowed in kernel_launch)
__device__ float g_ztT [C_DIM * N_TOT];    // [C][N]  z transposed: 16 MB
__device__ float g_embT[C_DIM * K_CODES];  // [C][K]  emb transposed: 8 MB
__device__ float g_ehalf[K_CODES];         // 0.5*||e_k||^2
__device__ int   g_idx  [N_TOT];           // argmin indices

// ---------------------------------------------------------------------------
// Pass 1: z [B][C][HW] -> ztT [C][B*HW].  Both read and write coalesced (hw
// is innermost on both sides).
// ---------------------------------------------------------------------------
__global__ void k_zt(const float* __restrict__ z) {
    int idx = blockIdx.x * blockDim.x + threadIdx.x;   // z-linear order (b,c,hw)
    int hw = idx & (HW - 1);
    int c  = (idx >> 10) & (C_DIM - 1);
    int b  = idx >> 18;                                 // / (C_DIM*HW)
    g_ztT[c * N_TOT + b * HW + hw] = z[idx];
}

// ---------------------------------------------------------------------------
// Pass 2: embT[c][k] = emb[k][c].  Standard tiled 32x32 transpose.
// grid (C/32, K/32), block (32,8)
// ---------------------------------------------------------------------------
__global__ void k_embT(const float* __restrict__ emb) {
    __shared__ float tile[32][33];
    int c0 = blockIdx.x * 32;
    int k0 = blockIdx.y * 32;
    int tx = threadIdx.x, ty = threadIdx.y;
    #pragma unroll
    for (int i = 0; i < 32; i += 8)
        tile[ty + i][tx] = emb[(k0 + ty + i) * C_DIM + c0 + tx];
    __syncthreads();
    #pragma unroll
    for (int i = 0; i < 32; i += 8)
        g_embT[(c0 + ty + i) * K_CODES + k0 + tx] = tile[tx][ty + i];
}

// ---------------------------------------------------------------------------
// Pass 3: g_ehalf[k] = 0.5 * sum_c emb[k][c]^2.  One warp per code.
// ---------------------------------------------------------------------------
__global__ void k_ehalf(const float* __restrict__ emb) {
    int k    = blockIdx.x * (blockDim.x >> 5) + (threadIdx.x >> 5);
    int lane = threadIdx.x & 31;
    const float* row = emb + k * C_DIM;
    float s = 0.0f;
    #pragma unroll
    for (int c = lane; c < C_DIM; c += 32) { float v = row[c]; s = fmaf(v, v, s); }
    #pragma unroll
    for (int off = 16; off; off >>= 1) s += __shfl_xor_sync(0xffffffffu, s, off);
    if (lane == 0) g_ehalf[k] = 0.5f * s;
}

// ---------------------------------------------------------------------------
// Main: fused fp32 GEMM + running argmax.
//   score[m][k] = z_m . e_k - 0.5*||e_k||^2 ; idx[m] = argmax_k score
// CTA: 128 rows x (loop over 64 tiles of 128 codes), 256 threads, 8x8 regs.
// Double-buffered smem (8 C-chunks at a time), register-staged prefetch.
// ---------------------------------------------------------------------------
__global__ __launch_bounds__(256, 1) void k_main() {
    __shared__ float As[2][8][128];   // [buf][cc][row]
    __shared__ float Bs[2][8][128];   // [buf][cc][code]

    const int tid   = threadIdx.x;
    const int m0    = blockIdx.x * 128;
    const int a_row = tid >> 5;             // 0..7   (C-chunk lane)
    const int a_col = (tid & 31) << 2;      // 0..124 (float4 column)
    const int ty    = tid >> 4, tx = tid & 15;
    const int ty8   = ty << 3,  tx8 = tx << 3;

    float best[8];
    int   bidx[8];
    #pragma unroll
    for (int i = 0; i < 8; i++) { best[i] = -1e30f; bidx[i] = 0; }

    // prefetch chunk (t=0,q=0)
    {
        float4 ra = *(const float4*)&g_ztT [a_row * N_TOT   + m0 + a_col];
        float4 rb = *(const float4*)&g_embT[a_row * K_CODES +      a_col];
        *(float4*)&As[0][a_row][a_col] = ra;
        *(float4*)&Bs[0][a_row][a_col] = rb;
    }
    __syncthreads();

    int buf = 0;
    for (int t = 0; t < 64; ++t) {
        const int k0 = t << 7;

        // fold -0.5||e||^2 into the accumulator init
        float eh[8];
        *(float4*)&eh[0] = *(const float4*)&g_ehalf[k0 + tx8];
        *(float4*)&eh[4] = *(const float4*)&g_ehalf[k0 + tx8 + 4];
        float acc[8][8];
        #pragma unroll
        for (int i = 0; i < 8; i++)
            #pragma unroll
            for (int j = 0; j < 8; j++)
                acc[i][j] = -eh[j];

        for (int q = 0; q < 32; ++q) {
            const int u = (t << 5) + q;
            const bool has_next = (u != 2047);
            float4 na, nb;
            if (has_next) {
                int qn  = (q == 31) ? 0 : q + 1;
                int tn  = (q == 31) ? t + 1 : t;
                int c0n = qn << 3;
                int k0n = tn << 7;
                na = *(const float4*)&g_ztT [(c0n + a_row) * N_TOT   + m0  + a_col];
                nb = *(const float4*)&g_embT[(c0n + a_row) * K_CODES + k0n + a_col];
            }
            #pragma unroll
            for (int cc = 0; cc < 8; ++cc) {
                float a[8], b[8];
                *(float4*)&a[0] = *(const float4*)&As[buf][cc][ty8];
                *(float4*)&a[4] = *(const float4*)&As[buf][cc][ty8 + 4];
                *(float4*)&b[0] = *(const float4*)&Bs[buf][cc][tx8];
                *(float4*)&b[4] = *(const float4*)&Bs[buf][cc][tx8 + 4];
                #pragma unroll
                for (int i = 0; i < 8; i++)
                    #pragma unroll
                    for (int j = 0; j < 8; j++)
                        acc[i][j] = fmaf(a[i], b[j], acc[i][j]);
            }
            if (has_next) {
                *(float4*)&As[buf ^ 1][a_row][a_col] = na;
                *(float4*)&Bs[buf ^ 1][a_row][a_col] = nb;
            }
            __syncthreads();
            buf ^= 1;
        }

        // per-thread running argmax (codes scanned in increasing order;
        // strict > keeps the lowest index on ties, matching jnp.argmin)
        #pragma unroll
        for (int j = 0; j < 8; j++) {
            const int code = k0 + tx8 + j;
            #pragma unroll
            for (int i = 0; i < 8; i++) {
                if (acc[i][j] > best[i]) { best[i] = acc[i][j]; bidx[i] = code; }
            }
        }
    }

    // reduce across the 16 threads (tx) sharing each row; width-16 butterfly
    #pragma unroll
    for (int i = 0; i < 8; i++) {
        float v = best[i];
        int   ix = bidx[i];
        #pragma unroll
        for (int off = 8; off; off >>= 1) {
            float v2 = __shfl_xor_sync(0xffffffffu, v,  off, 16);
            int   x2 = __shfl_xor_sync(0xffffffffu, ix, off, 16);
            if (v2 > v || (v2 == v && x2 < ix)) { v = v2; ix = x2; }
        }
        if (tx == 0) g_idx[m0 + ty8 + i] = ix;
    }
}

// ---------------------------------------------------------------------------
// Gather: out[b][c][hw] = emb[idx[b*HW+hw]][c].
// 32 n's per block via padded smem tile; emb-row reads coalesced, [B,C,H,W]
// writes coalesced (32 consecutive hw per c).
// ---------------------------------------------------------------------------
__global__ void k_gather(const float* __restrict__ emb, float* __restrict__ out) {
    __shared__ float tile[32 * 257];
    __shared__ int   sidx[32];
    const int nb  = blockIdx.x * 32;
    const int tid = threadIdx.x;
    if (tid < 32) sidx[tid] = g_idx[nb + tid];
    __syncthreads();

    const int w = tid >> 5, lane = tid & 31;
    #pragma unroll
    for (int r = w * 4; r < w * 4 + 4; ++r) {
        const float* src = emb + (size_t)sidx[r] * C_DIM;
        #pragma unroll
        for (int c = lane; c < C_DIM; c += 32)
            tile[r * 257 + c] = src[c];
    }
    __syncthreads();

    const int b   = nb >> 10;
    const int hw0 = nb & (HW - 1);
    const int cg  = tid >> 5;   // 0..7
    #pragma unroll
    for (int c = cg; c < C_DIM; c += 8)
        out[b * (C_DIM * HW) + c * HW + hw0 + lane] = tile[lane * 257 + c];
}

// ---------------------------------------------------------------------------
extern "C" void kernel_launch(void* const* d_in, const int* in_sizes, int n_in,
                              void* d_out, int out_size) {
    const float* z   = (const float*)d_in[0];   // [16,256,32,32] fp32
    const float* emb = (const float*)d_in[1];   // [8192,256] fp32
    float* out = (float*)d_out;                 // [16,256,32,32] fp32

    k_zt    <<<(B_DIM * C_DIM * HW) / 256, 256>>>(z);
    k_embT  <<<dim3(C_DIM / 32, K_CODES / 32), dim3(32, 8)>>>(emb);
    k_ehalf <<<K_CODES / 8, 256>>>(emb);
    k_main  <<<N_TOT / 128, 256>>>();
    k_gather<<<N_TOT / 32, 256>>>(emb, out);
}